// round 3
// baseline (speedup 1.0000x reference)
#include <cuda_runtime.h>
#include <cuda_bf16.h>

#define B_ 32
#define N_ 16384
#define D_ 256
#define S_ 8
#define CHUNKS 64
#define ROWS_PER_BLOCK (N_ / CHUNKS)   // 256
#define THREADS 256                    // 8 warps, 32 rows each
#define EPSN 1e-12f

// ---- scratch (device globals: no allocations allowed) ----
__device__ float g_score[B_ * N_];    // saliency * running mask
__device__ float g_invn[B_ * N_];     // 1 / max(||row||, eps)
__device__ float g_sel[B_ * D_];      // currently selected raw row per batch
__device__ float g_invsel[B_];        // 1 / max(||sel||, eps)
__device__ float g_pval[B_ * CHUNKS]; // per-block argmax partial value
__device__ int   g_pidx[B_ * CHUNKS]; // per-block argmax partial index

// -----------------------------------------------------------------------------
// Pass 0: per-row L2 norm -> score/invn, plus per-block argmax of saliency
// grid = B*CHUNKS blocks of 256 threads; warp w handles 32 consecutive rows.
// -----------------------------------------------------------------------------
__global__ void pre_kernel(const float* __restrict__ f) {
    int blk  = blockIdx.x;
    int b    = blk / CHUNKS;
    int c    = blk % CHUNKS;
    int warp = threadIdx.x >> 5;
    int lane = threadIdx.x & 31;
    int row0 = c * ROWS_PER_BLOCK + warp * 32;

    float bestV = -1.0f;
    int   bestI = 0x7fffffff;

    for (int r = 0; r < 32; ++r) {
        int row = row0 + r;
        const float4* p = (const float4*)(f + ((size_t)b * N_ + row) * D_);
        float4 a  = p[lane];
        float4 bb = p[lane + 32];
        float s = a.x*a.x + a.y*a.y + a.z*a.z + a.w*a.w
                + bb.x*bb.x + bb.y*bb.y + bb.z*bb.z + bb.w*bb.w;
        #pragma unroll
        for (int o = 16; o; o >>= 1) s += __shfl_xor_sync(0xffffffffu, s, o);
        float nrm = sqrtf(s);
        if (lane == 0) {
            int gi = b * N_ + row;
            g_invn[gi]  = 1.0f / fmaxf(nrm, EPSN);
            g_score[gi] = nrm;          // saliency * mask(==1)
        }
        if (nrm > bestV) { bestV = nrm; bestI = row; }  // strict > keeps lowest idx
    }

    __shared__ float sv[8];
    __shared__ int   si[8];
    if (lane == 0) { sv[warp] = bestV; si[warp] = bestI; }
    __syncthreads();
    if (threadIdx.x == 0) {
        float v = sv[0]; int i = si[0];
        #pragma unroll
        for (int w = 1; w < 8; ++w)
            if (sv[w] > v || (sv[w] == v && si[w] < i)) { v = sv[w]; i = si[w]; }
        g_pval[blk] = v;
        g_pidx[blk] = i;
    }
}

// -----------------------------------------------------------------------------
// Select: reduce 64 partials -> idx; copy row to out & g_sel; compute invsel.
// grid = B blocks of 256 threads (== D).
// -----------------------------------------------------------------------------
__global__ void select_kernel(const float* __restrict__ f,
                              float* __restrict__ out, int s) {
    int b = blockIdx.x;
    int t = threadIdx.x;

    __shared__ float rv[CHUNKS];
    __shared__ int   ri[CHUNKS];
    __shared__ int   s_idx;
    if (t < CHUNKS) { rv[t] = g_pval[b * CHUNKS + t]; ri[t] = g_pidx[b * CHUNKS + t]; }
    __syncthreads();
    if (t == 0) {
        float v = rv[0]; int i = ri[0];
        for (int k = 1; k < CHUNKS; ++k)
            if (rv[k] > v || (rv[k] == v && ri[k] < i)) { v = rv[k]; i = ri[k]; }
        s_idx = i;
    }
    __syncthreads();
    int idx = s_idx;

    float x = f[((size_t)b * N_ + idx) * D_ + t];
    out[((size_t)b * S_ + s) * D_ + t] = x;
    g_sel[b * D_ + t] = x;

    float ss = x * x;
    #pragma unroll
    for (int o = 16; o; o >>= 1) ss += __shfl_xor_sync(0xffffffffu, ss, o);
    __shared__ float wsum[8];
    if ((t & 31) == 0) wsum[t >> 5] = ss;
    __syncthreads();
    if (t == 0) {
        float tot = 0.f;
        #pragma unroll
        for (int w = 0; w < 8; ++w) tot += wsum[w];
        g_invsel[b] = 1.0f / fmaxf(sqrtf(tot), EPSN);
    }
}

// -----------------------------------------------------------------------------
// Update: score *= (1 - clamp(cos(row, sel), 0, 1)); fused next-slot argmax.
// grid = B*CHUNKS blocks of 256 threads.
// -----------------------------------------------------------------------------
__global__ void update_kernel(const float* __restrict__ f) {
    int blk  = blockIdx.x;
    int b    = blk / CHUNKS;
    int c    = blk % CHUNKS;
    int t    = threadIdx.x;
    int warp = t >> 5;
    int lane = t & 31;

    __shared__ float ssel[D_];
    ssel[t] = g_sel[b * D_ + t];
    __syncthreads();

    float invsel = g_invsel[b];
    const float4* sel4 = (const float4*)ssel;
    float4 sA = sel4[lane];
    float4 sB = sel4[lane + 32];

    int row0 = c * ROWS_PER_BLOCK + warp * 32;
    float bestV = -1.0f;
    int   bestI = 0x7fffffff;

    for (int r = 0; r < 32; ++r) {
        int row = row0 + r;
        const float4* p = (const float4*)(f + ((size_t)b * N_ + row) * D_);
        float4 a  = p[lane];
        float4 bb = p[lane + 32];
        float d = a.x*sA.x + a.y*sA.y + a.z*sA.z + a.w*sA.w
                + bb.x*sB.x + bb.y*sB.y + bb.z*sB.z + bb.w*sB.w;
        #pragma unroll
        for (int o = 16; o; o >>= 1) d += __shfl_xor_sync(0xffffffffu, d, o);

        int gi = b * N_ + row;
        float sim  = d * g_invn[gi] * invsel;
        float supp = 1.0f - fminf(fmaxf(sim, 0.0f), 1.0f);
        float ns   = g_score[gi] * supp;
        if (lane == 0) g_score[gi] = ns;
        if (ns > bestV) { bestV = ns; bestI = row; }
    }

    __shared__ float sv[8];
    __shared__ int   si[8];
    if (lane == 0) { sv[warp] = bestV; si[warp] = bestI; }
    __syncthreads();
    if (threadIdx.x == 0) {
        float v = sv[0]; int i = si[0];
        #pragma unroll
        for (int w = 1; w < 8; ++w)
            if (sv[w] > v || (sv[w] == v && si[w] < i)) { v = sv[w]; i = si[w]; }
        g_pval[blk] = v;
        g_pidx[blk] = i;
    }
}

// -----------------------------------------------------------------------------
extern "C" void kernel_launch(void* const* d_in, const int* in_sizes, int n_in,
                              void* d_out, int out_size) {
    // features is the large fp32 input (B*N*D elements); scalars ride along.
    const float* f = nullptr;
    long best = -1;
    for (int i = 0; i < n_in; ++i) {
        if ((long)in_sizes[i] > best) { best = in_sizes[i]; f = (const float*)d_in[i]; }
    }
    float* out = (float*)d_out;

    pre_kernel<<<B_ * CHUNKS, THREADS>>>(f);
    for (int s = 0; s < S_; ++s) {
        select_kernel<<<B_, THREADS>>>(f, out, s);
        if (s < S_ - 1) update_kernel<<<B_ * CHUNKS, THREADS>>>(f);
    }
}

// round 4
// speedup vs baseline: 1.0275x; 1.0275x over previous
#include <cuda_runtime.h>
#include <cuda_fp16.h>

#define B_ 32
#define N_ 16384
#define D_ 256
#define S_ 8
#define CHUNKS 64
#define ROWS_PER_BLOCK (N_ / CHUNKS)   // 256
#define THREADS 256                    // 8 warps
#define EPSN 1e-12f
#define MAXC 512

// ---- scratch (device globals: no allocations allowed) ----
__device__ float  g_score[B_ * N_];                    // running score (approx after s>0)
__device__ __half g_fnorm[(size_t)B_ * N_ * D_];       // normalized rows, fp16 (256 MB)
__device__ float  g_selhist[(size_t)S_ * B_ * D_];     // exact fp32 selnorm history
__device__ float  g_salmax[B_];                        // exact max saliency per batch
__device__ float  g_pval[B_ * CHUNKS];                 // per-block argmax partial value
__device__ int    g_pidx[B_ * CHUNKS];                 // per-block argmax partial index

// Block-wide sum; every thread returns the same value (deterministic order).
__device__ __forceinline__ float block_reduce_sum(float v, float* red) {
    int lane = threadIdx.x & 31, warp = threadIdx.x >> 5;
    #pragma unroll
    for (int o = 16; o; o >>= 1) v += __shfl_xor_sync(0xffffffffu, v, o);
    if (lane == 0) red[warp] = v;
    __syncthreads();
    float tot = red[0] + red[1] + red[2] + red[3]
              + red[4] + red[5] + red[6] + red[7];
    __syncthreads();
    return tot;
}

// -----------------------------------------------------------------------------
// Pass 0: exact fp32 row norms -> score (saliency), fnorm fp16 write,
// per-block exact argmax of saliency. grid = B*CHUNKS x 256.
// -----------------------------------------------------------------------------
__global__ void pre_kernel(const float* __restrict__ f) {
    int blk  = blockIdx.x;
    int b    = blk / CHUNKS;
    int c    = blk % CHUNKS;
    int warp = threadIdx.x >> 5;
    int lane = threadIdx.x & 31;
    int row0 = c * ROWS_PER_BLOCK + warp * 32;

    float bestV = -1.0f;
    int   bestI = 0x7fffffff;

    #pragma unroll 2
    for (int r = 0; r < 32; ++r) {
        int row = row0 + r;
        size_t base = ((size_t)b * N_ + row) * D_;
        const float4* p = (const float4*)(f + base);
        float4 a  = p[2 * lane];
        float4 bb = p[2 * lane + 1];
        float s = a.x*a.x + a.y*a.y + a.z*a.z + a.w*a.w
                + bb.x*bb.x + bb.y*bb.y + bb.z*bb.z + bb.w*bb.w;
        #pragma unroll
        for (int o = 16; o; o >>= 1) s += __shfl_xor_sync(0xffffffffu, s, o);
        float nrm = sqrtf(s);
        float inv = 1.0f / fmaxf(nrm, EPSN);

        union { float4 v; __half2 h[4]; } u;
        u.h[0] = __floats2half2_rn(a.x * inv,  a.y * inv);
        u.h[1] = __floats2half2_rn(a.z * inv,  a.w * inv);
        u.h[2] = __floats2half2_rn(bb.x * inv, bb.y * inv);
        u.h[3] = __floats2half2_rn(bb.z * inv, bb.w * inv);
        *(float4*)(g_fnorm + base + (size_t)lane * 8) = u.v;

        if (lane == 0) g_score[b * N_ + row] = nrm;
        if (nrm > bestV) { bestV = nrm; bestI = row; }
    }

    __shared__ float sv[8];
    __shared__ int   si[8];
    if (lane == 0) { sv[warp] = bestV; si[warp] = bestI; }
    __syncthreads();
    if (threadIdx.x == 0) {
        float v = sv[0]; int i = si[0];
        #pragma unroll
        for (int w = 1; w < 8; ++w)
            if (sv[w] > v || (sv[w] == v && si[w] < i)) { v = sv[w]; i = si[w]; }
        g_pval[blk] = v;
        g_pidx[blk] = i;
    }
}

// -----------------------------------------------------------------------------
// Select with exact verification. grid = B x 256 (== D).
// 1) approx max from partials. 2) gather candidates within rigorous margin.
// 3) recompute candidate scores exactly in fp32. 4) exact argmax, write slot,
//    store exact selnorm for this slot.
// -----------------------------------------------------------------------------
__global__ void select_kernel(const float* __restrict__ f,
                              float* __restrict__ out, int s) {
    int b = blockIdx.x;
    int t = threadIdx.x;

    __shared__ float red[8];
    __shared__ float sh_m;
    __shared__ int   sh_cnt;
    __shared__ int   cand[MAXC];
    __shared__ float sh_bestV;
    __shared__ int   sh_bestI;

    if (t == 0) {
        float v = g_pval[b * CHUNKS]; int i = g_pidx[b * CHUNKS];
        for (int k = 1; k < CHUNKS; ++k) {
            float pv = g_pval[b * CHUNKS + k]; int pi = g_pidx[b * CHUNKS + k];
            if (pv > v || (pv == v && pi < i)) { v = pv; i = pi; }
        }
        sh_m = v;
        sh_cnt = 0;
        sh_bestV = -1.0f;
        sh_bestI = 0x7fffffff;
        if (s == 0) g_salmax[b] = v;   // exact max saliency
    }
    __syncthreads();

    // Rigorous bound on |score_approx - score_exact|:
    // per pass |dSim| <= 2^-11 * Sum|u_i v_i| <= ~5.1e-4 (selnorm exact fp32);
    // |dScore| <= salmax * s * 5.1e-4.  Gather threshold uses 2*eps with ~3x headroom.
    float margin = (s == 0) ? 0.0f : g_salmax[b] * (float)s * 3e-3f;
    float thr = sh_m - margin;

    for (int i = t; i < N_; i += THREADS) {
        if (g_score[b * N_ + i] >= thr) {
            int p = atomicAdd(&sh_cnt, 1);
            if (p < MAXC) cand[p] = i;
        }
    }
    __syncthreads();
    int nc = min(sh_cnt, MAXC);

    // Exact fp32 rescoring of candidates (uniform control flow across block).
    for (int ci = 0; ci < nc; ++ci) {
        int idx = cand[ci];
        float x = f[((size_t)b * N_ + idx) * D_ + t];
        float sal2 = block_reduce_sum(x * x, red);
        float sal  = sqrtf(sal2);
        float fn   = x / fmaxf(sal, EPSN);
        float supp = 1.0f;
        for (int j = 0; j < s; ++j) {
            float pj  = fn * g_selhist[((size_t)j * B_ + b) * D_ + t];
            float sim = block_reduce_sum(pj, red);
            supp *= (1.0f - fminf(fmaxf(sim, 0.0f), 1.0f));
        }
        if (t == 0) {
            float sc = sal * supp;
            if (sc > sh_bestV || (sc == sh_bestV && idx < sh_bestI)) {
                sh_bestV = sc; sh_bestI = idx;
            }
        }
        __syncthreads();
    }

    int w = sh_bestI;
    float x = f[((size_t)b * N_ + w) * D_ + t];
    out[((size_t)b * S_ + s) * D_ + t] = x;
    float sal2 = block_reduce_sum(x * x, red);
    float inv  = 1.0f / fmaxf(sqrtf(sal2), EPSN);
    g_selhist[((size_t)s * B_ + b) * D_ + t] = x * inv;   // exact fp32 selnorm
}

// -----------------------------------------------------------------------------
// Update: score *= (1 - clip(fnorm . selnorm)); fused per-block argmax.
// fnorm is fp16 (512 B/row): one float4 (8 halves) per lane, warp per row.
// grid = B*CHUNKS x 256.
// -----------------------------------------------------------------------------
__global__ void update_kernel(int s) {
    int blk  = blockIdx.x;
    int b    = blk / CHUNKS;
    int c    = blk % CHUNKS;
    int t    = threadIdx.x;
    int warp = t >> 5;
    int lane = t & 31;

    __shared__ float ssel[D_];
    ssel[t] = g_selhist[((size_t)s * B_ + b) * D_ + t];
    __syncthreads();

    float se[8];
    #pragma unroll
    for (int k = 0; k < 8; ++k) se[k] = ssel[lane * 8 + k];

    int row0 = c * ROWS_PER_BLOCK + warp * 32;
    float bestV = -1.0f;
    int   bestI = 0x7fffffff;

    #pragma unroll 4
    for (int r = 0; r < 32; ++r) {
        int row = row0 + r;
        size_t base = ((size_t)b * N_ + row) * D_;
        float4 raw = *(const float4*)(g_fnorm + base + (size_t)lane * 8);
        __half2* h = (__half2*)&raw;
        float d = 0.0f;
        #pragma unroll
        for (int k = 0; k < 4; ++k) {
            float2 f2 = __half22float2(h[k]);
            d = fmaf(f2.x, se[2 * k],     d);
            d = fmaf(f2.y, se[2 * k + 1], d);
        }
        #pragma unroll
        for (int o = 16; o; o >>= 1) d += __shfl_xor_sync(0xffffffffu, d, o);

        int gi = b * N_ + row;
        float ns = g_score[gi] * (1.0f - fminf(fmaxf(d, 0.0f), 1.0f));
        if (lane == 0) g_score[gi] = ns;
        if (ns > bestV) { bestV = ns; bestI = row; }
    }

    __shared__ float sv[8];
    __shared__ int   si[8];
    if (lane == 0) { sv[warp] = bestV; si[warp] = bestI; }
    __syncthreads();
    if (threadIdx.x == 0) {
        float v = sv[0]; int i = si[0];
        #pragma unroll
        for (int w2 = 1; w2 < 8; ++w2)
            if (sv[w2] > v || (sv[w2] == v && si[w2] < i)) { v = sv[w2]; i = si[w2]; }
        g_pval[blk] = v;
        g_pidx[blk] = i;
    }
}

// -----------------------------------------------------------------------------
extern "C" void kernel_launch(void* const* d_in, const int* in_sizes, int n_in,
                              void* d_out, int out_size) {
    const float* f = nullptr;
    long best = -1;
    for (int i = 0; i < n_in; ++i) {
        if ((long)in_sizes[i] > best) { best = in_sizes[i]; f = (const float*)d_in[i]; }
    }
    float* out = (float*)d_out;

    pre_kernel<<<B_ * CHUNKS, THREADS>>>(f);
    for (int s = 0; s < S_; ++s) {
        select_kernel<<<B_, THREADS>>>(f, out, s);
        if (s < S_ - 1) update_kernel<<<B_ * CHUNKS, THREADS>>>(s);
    }
}